// round 12
// baseline (speedup 1.0000x reference)
#include <cuda_runtime.h>
#include <cuda_fp16.h>
#include <cuda_bf16.h>
#include <math.h>
#include <stdint.h>

#define TT 128
#define BB 512
#define HH 256
#define MM 64

__device__ __half g_sentWh[(size_t)TT * BB * HH];   // stories @ W (fp16)
__device__ __half g_storiesh[(size_t)TT * BB * HH]; // stories (fp16)
__device__ float  g_kdot[(size_t)TT * MM * BB];     // keys[m] . sent[t,b] (fp32)
__device__ __half g_Uth[HH * HH];                   // U^T fp16 [n][k]
__device__ __nv_bfloat16 g_Wthi[HH * HH];
__device__ __nv_bfloat16 g_Wtlo[HH * HH];

// ---------------- helpers ----------------
__device__ __forceinline__ unsigned smem_u32(const void* p) {
    return (unsigned)__cvta_generic_to_shared(p);
}
__device__ __forceinline__ void ldsm_x4(unsigned addr, unsigned& r0, unsigned& r1, unsigned& r2, unsigned& r3) {
    asm volatile("ldmatrix.sync.aligned.m8n8.x4.shared.b16 {%0,%1,%2,%3}, [%4];"
                 : "=r"(r0), "=r"(r1), "=r"(r2), "=r"(r3) : "r"(addr));
}
__device__ __forceinline__ void mma_bf16(float* c, const unsigned* a, unsigned b0, unsigned b1) {
    asm volatile("mma.sync.aligned.m16n8k16.row.col.f32.bf16.bf16.f32 "
                 "{%0,%1,%2,%3}, {%4,%5,%6,%7}, {%8,%9}, {%0,%1,%2,%3};"
                 : "+f"(c[0]), "+f"(c[1]), "+f"(c[2]), "+f"(c[3])
                 : "r"(a[0]), "r"(a[1]), "r"(a[2]), "r"(a[3]), "r"(b0), "r"(b1));
}
__device__ __forceinline__ void mma_f16(float* c, const unsigned* a, unsigned b0, unsigned b1) {
    asm volatile("mma.sync.aligned.m16n8k16.row.col.f32.f16.f16.f32 "
                 "{%0,%1,%2,%3}, {%4,%5,%6,%7}, {%8,%9}, {%0,%1,%2,%3};"
                 : "+f"(c[0]), "+f"(c[1]), "+f"(c[2]), "+f"(c[3])
                 : "r"(a[0]), "r"(a[1]), "r"(a[2]), "r"(a[3]), "r"(b0), "r"(b1));
}
__device__ __forceinline__ void cpasync16(unsigned dst, const void* src) {
    asm volatile("cp.async.cg.shared.global [%0], [%1], 16;" :: "r"(dst), "l"(src));
}
__device__ __forceinline__ unsigned pack2bf(__nv_bfloat16 a, __nv_bfloat16 b) {
    unsigned short ua = *reinterpret_cast<unsigned short*>(&a);
    unsigned short ub = *reinterpret_cast<unsigned short*>(&b);
    return (unsigned)ua | ((unsigned)ub << 16);
}
__device__ __forceinline__ uint32_t h2u(__half2 v) {
    union { __half2 h; uint32_t u; } c; c.h = v; return c.u;
}
__device__ __forceinline__ __half2 u2h(uint32_t v) {
    union { __half2 h; uint32_t u; } c; c.u = v; return c.h;
}
__device__ __forceinline__ void split8(float4 v0, float4 v1, uint4& h, uint4& l) {
    float f[8] = {v0.x, v0.y, v0.z, v0.w, v1.x, v1.y, v1.z, v1.w};
    unsigned hh[4], ll[4];
#pragma unroll
    for (int j = 0; j < 4; j++) {
        float a = f[2 * j], b = f[2 * j + 1];
        __nv_bfloat16 ha = __float2bfloat16(a), hb = __float2bfloat16(b);
        __nv_bfloat16 la = __float2bfloat16(a - __bfloat162float(ha));
        __nv_bfloat16 lb = __float2bfloat16(b - __bfloat162float(hb));
        hh[j] = pack2bf(ha, hb); ll[j] = pack2bf(la, lb);
    }
    h = make_uint4(hh[0], hh[1], hh[2], hh[3]);
    l = make_uint4(ll[0], ll[1], ll[2], ll[3]);
}

// ---------------- prep ----------------
__global__ void split_transpose_kernel(const float* __restrict__ src,
                                       __nv_bfloat16* __restrict__ hi,
                                       __nv_bfloat16* __restrict__ lo) {
    int idx = blockIdx.x * 256 + threadIdx.x;
    int n = idx >> 8, k = idx & 255;
    float x = src[k * 256 + n];
    __nv_bfloat16 h = __float2bfloat16(x);
    hi[idx] = h;
    lo[idx] = __float2bfloat16(x - __bfloat162float(h));
}
__global__ void prep_Uth_kernel(const float* __restrict__ U) {
    int idx = blockIdx.x * 256 + threadIdx.x;
    int n = idx >> 8, k = idx & 255;
    g_Uth[idx] = __float2half(U[k * 256 + n]);
}
__global__ void stories_half_kernel(const float* __restrict__ src) {
    size_t i = ((size_t)blockIdx.x * 256 + threadIdx.x) * 4;
    float4 v = *(const float4*)(src + i);
    __half2* d = (__half2*)(g_storiesh + i);
    d[0] = __float22half2_rn(make_float2(v.x, v.y));
    d[1] = __float22half2_rn(make_float2(v.z, v.w));
}

// kdot[t][m][b] = stories[t,b,:] . keys[m,:]
#define KD_SK_STR 72
#define KD_SE_STR 33
#define KD_SMEM ((256 * KD_SK_STR + 256 * KD_SE_STR) * 4)
__global__ __launch_bounds__(256) void kdot_kernel(const float* __restrict__ stories,
                                                   const float* __restrict__ keys) {
    extern __shared__ float sh[];
    float* sK = sh;                          // [256 k][72] (64 m)
    float* sS = sh + 256 * KD_SK_STR;        // [256 b][33] (32-k chunk)
    const int tid = threadIdx.x;
    const int t = blockIdx.x;
    const int bh = blockIdx.y;
    const float* sent = stories + (((size_t)t * BB) + bh * 256) * HH;

    for (int i = tid; i < MM * HH; i += 256) {
        int m = i >> 8, k = i & 255;
        sK[k * KD_SK_STR + m] = keys[i];
    }

    float4 acc[16];
#pragma unroll
    for (int i = 0; i < 16; i++) acc[i] = make_float4(0.f, 0.f, 0.f, 0.f);

    for (int kc = 0; kc < 8; kc++) {
        __syncthreads();
        for (int i = tid; i < 2048; i += 256) {
            int row = i >> 3, kq = (i & 7) * 4;
            float4 v = *(const float4*)(sent + (size_t)row * HH + kc * 32 + kq);
            float* dst = sS + row * KD_SE_STR + kq;
            dst[0] = v.x; dst[1] = v.y; dst[2] = v.z; dst[3] = v.w;
        }
        __syncthreads();
#pragma unroll 4
        for (int kk = 0; kk < 32; kk++) {
            float v = sS[tid * KD_SE_STR + kk];
            const float4* kr = (const float4*)(sK + (kc * 32 + kk) * KD_SK_STR);
#pragma unroll
            for (int m4 = 0; m4 < 16; m4++) {
                float4 kv = kr[m4];
                acc[m4].x += v * kv.x; acc[m4].y += v * kv.y;
                acc[m4].z += v * kv.z; acc[m4].w += v * kv.w;
            }
        }
    }
    const float* accf = (const float*)acc;
#pragma unroll
    for (int m = 0; m < 64; m++)
        g_kdot[(((size_t)t * MM) + m) * BB + bh * 256 + tid] = accf[m];
}

// ---------------- sentW precompute (bf16 3-pass, fp16 out) ----------------
#define SA_STR 264
#define SA_BYTES (128 * SA_STR * 2)
#define SBC_STR 40
#define SBC_BYTES (256 * SBC_STR * 2)
#define OFF_AHI 0
#define OFF_ALO SA_BYTES
#define OFF_B (2 * SA_BYTES)
#define G_SMEM (OFF_B + 4 * SBC_BYTES + 1024)

__device__ __forceinline__ void g_stage_A(const float* __restrict__ Asrc, char* sm, int tid) {
    __nv_bfloat16* sAhi = (__nv_bfloat16*)(sm + OFF_AHI);
    __nv_bfloat16* sAlo = (__nv_bfloat16*)(sm + OFF_ALO);
    for (int i = tid; i < 128 * 32; i += 512) {
        int row = i >> 5, kq = (i & 31) << 3;
        const float* p = Asrc + row * 256 + kq;
        float4 v0 = *(const float4*)p;
        float4 v1 = *(const float4*)(p + 4);
        uint4 h, l;
        split8(v0, v1, h, l);
        *(uint4*)(sAhi + row * SA_STR + kq) = h;
        *(uint4*)(sAlo + row * SA_STR + kq) = l;
    }
}
__device__ __forceinline__ void g_stage_B(char* sm, const __nv_bfloat16* __restrict__ Bthi,
                                          const __nv_bfloat16* __restrict__ Btlo,
                                          int buf, int kt, int tid) {
    __nv_bfloat16* bh = (__nv_bfloat16*)(sm + OFF_B + buf * 2 * SBC_BYTES);
    __nv_bfloat16* bl = (__nv_bfloat16*)(sm + OFF_B + buf * 2 * SBC_BYTES + SBC_BYTES);
    for (int i = tid; i < 1024; i += 512) {
        int n = i >> 2, g = (i & 3) << 3;
        cpasync16(smem_u32(bh + n * SBC_STR + g), Bthi + n * 256 + kt + g);
        cpasync16(smem_u32(bl + n * SBC_STR + g), Btlo + n * 256 + kt + g);
    }
}

__global__ __launch_bounds__(512, 1) void tc_gemm_kernel(const float* __restrict__ Asrc,
                                                         __half* __restrict__ Cout) {
    extern __shared__ char sm[];
    const int tid = threadIdx.x;
    const int lane = tid & 31, wid = tid >> 5;
    const int wr = wid >> 2, wc = wid & 3;
    const int rb = wr * 32;
    const size_t row0 = (size_t)blockIdx.x * 128;
    const int a_lr = ((lane >> 3) & 1) * 8 + (lane & 7);
    const int a_lc = ((lane >> 4) & 1) * 8;
    const int b_nr = ((lane >> 4) << 3) + (lane & 7);
    const int b_kc = ((lane >> 3) & 1) << 3;
    const unsigned sAhiU = smem_u32(sm + OFF_AHI);
    const unsigned sAloU = smem_u32(sm + OFF_ALO);
    const unsigned sB0 = smem_u32(sm + OFF_B);

    g_stage_A(Asrc + row0 * 256, sm, tid);
    __syncthreads();

    float acc[2][8][4];
#pragma unroll
    for (int i = 0; i < 2; i++)
#pragma unroll
        for (int j = 0; j < 8; j++)
#pragma unroll
            for (int q = 0; q < 4; q++) acc[i][j][q] = 0.f;

    g_stage_B(sm, g_Wthi, g_Wtlo, 0, 0, tid);
    asm volatile("cp.async.commit_group;");

#pragma unroll 2
    for (int c = 0; c < 8; c++) {
        if (c < 7) {
            g_stage_B(sm, g_Wthi, g_Wtlo, (c + 1) & 1, (c + 1) * 32, tid);
            asm volatile("cp.async.commit_group;");
            asm volatile("cp.async.wait_group 1;");
        } else {
            asm volatile("cp.async.wait_group 0;");
        }
        __syncthreads();
        const unsigned sBhiU = sB0 + (c & 1) * 2 * SBC_BYTES;
        const unsigned sBloU = sBhiU + SBC_BYTES;
#pragma unroll
        for (int ks = 0; ks < 2; ks++) {
            int kA = c * 32 + ks * 16;
            unsigned Ah[2][4], Al[2][4];
#pragma unroll
            for (int mi = 0; mi < 2; mi++) {
                unsigned aoff = (unsigned)((rb + mi * 16 + a_lr) * SA_STR + kA + a_lc) * 2;
                ldsm_x4(sAhiU + aoff, Ah[mi][0], Ah[mi][1], Ah[mi][2], Ah[mi][3]);
                ldsm_x4(sAloU + aoff, Al[mi][0], Al[mi][1], Al[mi][2], Al[mi][3]);
            }
#pragma unroll
            for (int np = 0; np < 4; np++) {
                unsigned boff = (unsigned)((wc * 64 + np * 16 + b_nr) * SBC_STR + ks * 16 + b_kc) * 2;
                unsigned Bh[4], Bl[4];
                ldsm_x4(sBhiU + boff, Bh[0], Bh[1], Bh[2], Bh[3]);
                ldsm_x4(sBloU + boff, Bl[0], Bl[1], Bl[2], Bl[3]);
#pragma unroll
                for (int mi = 0; mi < 2; mi++) {
#pragma unroll
                    for (int nj = 0; nj < 2; nj++) {
                        float* cc = acc[mi][np * 2 + nj];
                        mma_bf16(cc, Ah[mi], Bh[2 * nj], Bh[2 * nj + 1]);
                        mma_bf16(cc, Ah[mi], Bl[2 * nj], Bl[2 * nj + 1]);
                        mma_bf16(cc, Al[mi], Bh[2 * nj], Bh[2 * nj + 1]);
                    }
                }
            }
        }
        __syncthreads();
    }

    const int gid = lane >> 2, tig = lane & 3;
#pragma unroll
    for (int mi = 0; mi < 2; mi++) {
        int r0 = rb + mi * 16 + gid, r1 = r0 + 8;
#pragma unroll
        for (int nt = 0; nt < 8; nt++) {
            int C = wc * 64 + nt * 8 + tig * 2;
            float* cc = acc[mi][nt];
            *(__half2*)(Cout + (row0 + r0) * 256 + C) = __float22half2_rn(make_float2(cc[0], cc[1]));
            *(__half2*)(Cout + (row0 + r1) * 256 + C) = __float22half2_rn(make_float2(cc[2], cc[3]));
        }
    }
}

// ================= persistent recurrence (512 thr, sw prefetch, kdot) ======
#define P_SA_STR 264
#define P_SA_BYTES (64 * P_SA_STR * 2)         // 33792
#define P_BH_STR 264
#define P_BH_BYTES (256 * P_BH_STR * 2)        // 135168
#define P_OFF_A 0
#define P_OFF_B P_SA_BYTES
#define P_OFF_SW (P_OFF_B + P_BH_BYTES)        // 168960; [64][256] fp16
#define P_SW_BYTES (64 * 256 * 2)              // 32768
#define P_OFF_F32 (P_OFF_SW + P_SW_BYTES)      // 201728
// f32: kc256 pa256 gm64 sc64 ss256 g1_256
#define P_SMEM (P_OFF_F32 + (256 + 256 + 64 + 64 + 256 + 256) * 4)   // 206336

__global__ __launch_bounds__(512, 1) void persist_kernel(const float* __restrict__ mask,
                                                         const float* __restrict__ keys,
                                                         const float* __restrict__ V,
                                                         const float* __restrict__ prelu_a,
                                                         float* __restrict__ out) {
    extern __shared__ char sm[];
    __half* sA  = (__half*)(sm + P_OFF_A);
    __half* sB  = (__half*)(sm + P_OFF_B);
    __half* sSW = (__half*)(sm + P_OFF_SW);
    float* sKC = (float*)(sm + P_OFF_F32);
    float* sPA = sKC + 256;
    float* sGm = sPA + 256;   // [64]
    float* sSc = sGm + 64;    // [64]
    float* sSS = sSc + 64;    // [64][4]
    float* sG1 = sSS + 256;   // [64][4]

    const int tid = threadIdx.x;
    const int lane = tid & 31, wid = tid >> 5;
    const int wr = wid >> 2, wc = wid & 3;
    const int rb = wr * 16;
    const int gid = lane >> 2, tig = lane & 3;
    const int m = blockIdx.y;
    const int b0 = blockIdx.x * 64;

    const int a_lr = ((lane >> 3) & 1) * 8 + (lane & 7);
    const int a_lc = ((lane >> 4) & 1) * 8;
    const int b_nr = ((lane >> 4) << 3) + (lane & 7);
    const int b_kc = ((lane >> 3) & 1) << 3;
    const unsigned sAU = smem_u32(sA), sBU = smem_u32(sB), sSWU = smem_u32(sSW);

    float* __restrict__ gates_out = out + (size_t)MM * BB * HH;

    if (tid < 256) {
        sPA[tid] = prelu_a[tid];
        float p = 0.f;
        const float* vp = V + tid;
        const float* kp = keys + m * HH;
#pragma unroll 8
        for (int k = 0; k < 256; k++) p += kp[k] * vp[(size_t)k * HH];
        sKC[tid] = p;
    }
    // resident U^T fp16
    for (int i = tid; i < 256 * 32; i += 512) {
        int n = i >> 5, g = (i & 31) << 3;
        *(uint4*)(sB + n * P_BH_STR + g) = *(const uint4*)(g_Uth + n * 256 + g);
    }
    // init state rows = keys[m] raw, scale 1
    for (int i = tid; i < 64 * 32; i += 512) {
        int row = i >> 5, kq = (i & 31) << 3;
#pragma unroll
        for (int j = 0; j < 4; j++) {
            float2 kv = *(const float2*)(keys + m * HH + kq + 2 * j);
            *(uint32_t*)(sA + row * P_SA_STR + kq + 2 * j) = h2u(__float22half2_rn(kv));
        }
    }
    // gate 0 from kdot; scale 1
    if (tid < 64) {
        sSc[tid] = 1.0f;
        float g = 1.0f / (1.0f + expf(-2.0f * g_kdot[(size_t)m * BB + b0 + tid]));
        gates_out[(size_t)m * BB + b0 + tid] = g;
        sGm[tid] = g * mask[b0 + tid];
    }
    __syncthreads();

    for (int t = 0; t < TT; t++) {
        // prefetch this step's sentW tile (consumed after the mma)
        {
            const __half* swsrc = g_sentWh + ((size_t)t * BB + b0) * HH;
            for (int i = tid; i < 2048; i += 512) {
                int row = i >> 5, g = (i & 31) << 3;
                cpasync16(sSWU + (unsigned)(row * 256 + g) * 2, swsrc + (size_t)row * 256 + g);
            }
            asm volatile("cp.async.commit_group;");
        }

        // ---- mma: D = raw_state @ U (barrier-free, single pass) ----
        float acc[8][4];
#pragma unroll
        for (int j = 0; j < 8; j++)
#pragma unroll
            for (int q = 0; q < 4; q++) acc[j][q] = 0.f;

#pragma unroll 4
        for (int ks = 0; ks < 16; ks++) {
            int kcol = ks * 16;
            unsigned Af[4];
            unsigned aoff = (unsigned)((rb + a_lr) * P_SA_STR + kcol + a_lc) * 2;
            ldsm_x4(sAU + aoff, Af[0], Af[1], Af[2], Af[3]);
#pragma unroll
            for (int np = 0; np < 4; np++) {
                unsigned boff = (unsigned)((wc * 64 + np * 16 + b_nr) * P_BH_STR + kcol + b_kc) * 2;
                unsigned Bf[4];
                ldsm_x4(sBU + boff, Bf[0], Bf[1], Bf[2], Bf[3]);
#pragma unroll
                for (int nj = 0; nj < 2; nj++)
                    mma_f16(acc[np * 2 + nj], Af, Bf[2 * nj], Bf[2 * nj + 1]);
            }
        }
        asm volatile("cp.async.wait_group 0;");
        __syncthreads();   // all warps done reading sA; sSW complete

        // ---- fused epilogue + next-gate partials ----
        const int tn = (t < TT - 1) ? t + 1 : t;
        const __half* seb = g_storiesh + ((size_t)tn * BB + b0) * HH;
        {
            int r0 = rb + gid, r1 = r0 + 8;
            float gm0 = sGm[r0], gm1 = sGm[r1];
            float s0 = sSc[r0], s1 = sSc[r1];
            float ss0 = 0.f, ss1 = 0.f, g1a = 0.f, g1b = 0.f;
#pragma unroll
            for (int nt = 0; nt < 8; nt++) {
                int C = wc * 64 + nt * 8 + tig * 2;
                float2 kc = *(const float2*)(sKC + C);
                float2 pa = *(const float2*)(sPA + C);
                float2 sw0 = __half22float2(*(const __half2*)(sSW + r0 * 256 + C));
                float2 sw1 = __half22float2(*(const __half2*)(sSW + r1 * 256 + C));
                float2 se0 = __half22float2(*(const __half2*)(seb + (size_t)r0 * 256 + C));
                float2 se1 = __half22float2(*(const __half2*)(seb + (size_t)r1 * 256 + C));
                float2 o0 = __half22float2(u2h(*(const uint32_t*)(sA + r0 * P_SA_STR + C)));
                float2 o1 = __half22float2(u2h(*(const uint32_t*)(sA + r1 * P_SA_STR + C)));
                float* cc = acc[nt];
                float v, n0x, n0y, n1x, n1y;
                v = fmaf(s0, cc[0], kc.x + sw0.x); v = (v >= 0.f) ? v : pa.x * v; n0x = fmaf(gm0, v, s0 * o0.x);
                v = fmaf(s0, cc[1], kc.y + sw0.y); v = (v >= 0.f) ? v : pa.y * v; n0y = fmaf(gm0, v, s0 * o0.y);
                v = fmaf(s1, cc[2], kc.x + sw1.x); v = (v >= 0.f) ? v : pa.x * v; n1x = fmaf(gm1, v, s1 * o1.x);
                v = fmaf(s1, cc[3], kc.y + sw1.y); v = (v >= 0.f) ? v : pa.y * v; n1y = fmaf(gm1, v, s1 * o1.y);
                ss0 = fmaf(n0x, n0x, fmaf(n0y, n0y, ss0));
                ss1 = fmaf(n1x, n1x, fmaf(n1y, n1y, ss1));
                g1a = fmaf(n0x, se0.x, fmaf(n0y, se0.y, g1a));
                g1b = fmaf(n1x, se1.x, fmaf(n1y, se1.y, g1b));
                *(uint32_t*)(sA + r0 * P_SA_STR + C) = h2u(__float22half2_rn(make_float2(n0x, n0y)));
                *(uint32_t*)(sA + r1 * P_SA_STR + C) = h2u(__float22half2_rn(make_float2(n1x, n1y)));
            }
#pragma unroll
            for (int d = 1; d <= 2; d <<= 1) {
                ss0 += __shfl_xor_sync(0xffffffffu, ss0, d);
                ss1 += __shfl_xor_sync(0xffffffffu, ss1, d);
                g1a += __shfl_xor_sync(0xffffffffu, g1a, d);
                g1b += __shfl_xor_sync(0xffffffffu, g1b, d);
            }
            if (tig == 0) {
                atomicAdd(sSS + r0, 0.f);   // no-op placeholder removed by compiler? (kept simple below)
            }
            if (tig == 0) {
                sSS[r0 * 4 + wc] = ss0; sSS[r1 * 4 + wc] = ss1;
                sG1[r0 * 4 + wc] = g1a; sG1[r1 * 4 + wc] = g1b;
            }
        }
        __syncthreads();

        // ---- finalize: norm scale + next gate ----
        if (tid < 64) {
            int r = tid;
            float ssum = sSS[r * 4] + sSS[r * 4 + 1] + sSS[r * 4 + 2] + sSS[r * 4 + 3];
            float sc = 1.0f / fmaxf(sqrtf(ssum), 1e-12f);
            sSc[r] = sc;
            if (t < TT - 1) {
                float arg = sc * (sG1[r * 4] + sG1[r * 4 + 1] + sG1[r * 4 + 2] + sG1[r * 4 + 3])
                          + g_kdot[(((size_t)(t + 1) * MM) + m) * BB + b0 + r];
                float g = 1.0f / (1.0f + expf(-arg));
                gates_out[((size_t)(t + 1) * MM + m) * BB + b0 + r] = g;
                sGm[r] = g * mask[(t + 1) * BB + b0 + r];
            }
        }
        // next iteration's barrier (after mma) orders sSc/sGm for the epilogue
    }
    __syncthreads();

    // final output: normalized state
    for (int i = tid; i < 64 * 256; i += 512) {
        int row = i >> 8, col = i & 255;
        out[((size_t)m * BB + b0 + row) * HH + col] = __half2float(sA[row * P_SA_STR + col]) * sSc[row];
    }
}

// ---------------------------------------------------------------------------
extern "C" void kernel_launch(void* const* d_in, const int* in_sizes, int n_in,
                              void* d_out, int out_size) {
    const float* stories = (const float*)d_in[0];
    const float* mask    = (const float*)d_in[1];
    const float* keys    = (const float*)d_in[2];
    const float* U       = (const float*)d_in[3];
    const float* W       = (const float*)d_in[4];
    const float* V       = (const float*)d_in[5];
    const float* prelu_a = (const float*)d_in[6];
    float* out = (float*)d_out;

    static bool attr_done = false;
    if (!attr_done) {
        cudaFuncSetAttribute(tc_gemm_kernel, cudaFuncAttributeMaxDynamicSharedMemorySize, G_SMEM);
        cudaFuncSetAttribute(kdot_kernel,    cudaFuncAttributeMaxDynamicSharedMemorySize, KD_SMEM);
        cudaFuncSetAttribute(persist_kernel, cudaFuncAttributeMaxDynamicSharedMemorySize, P_SMEM);
        attr_done = true;
    }

    __nv_bfloat16 *wthi, *wtlo;
    cudaGetSymbolAddress((void**)&wthi, g_Wthi);
    cudaGetSymbolAddress((void**)&wtlo, g_Wtlo);
    __half* sentwh;
    cudaGetSymbolAddress((void**)&sentwh, g_sentWh);

    split_transpose_kernel<<<256, 256>>>(W, wthi, wtlo);
    prep_Uth_kernel<<<256, 256>>>(U);
    stories_half_kernel<<<(TT * BB * HH) / 1024, 256>>>(stories);
    dim3 kgrid(TT, BB / 256);
    kdot_kernel<<<kgrid, 256, KD_SMEM>>>(stories, keys);
    tc_gemm_kernel<<<(TT * BB) / 128, 512, G_SMEM>>>(stories, sentwh);

    dim3 grid(BB / 64, MM);
    persist_kernel<<<grid, 512, P_SMEM>>>(mask, keys, V, prelu_a, out);
}

// round 13
// speedup vs baseline: 1.0688x; 1.0688x over previous
#include <cuda_runtime.h>
#include <cuda_fp16.h>
#include <cuda_bf16.h>
#include <math.h>
#include <stdint.h>

#define TT 128
#define BB 512
#define HH 256
#define MM 64

__device__ __half g_sentWh[(size_t)TT * BB * HH];   // stories @ W (fp16)
__device__ __half g_storiesh[(size_t)TT * BB * HH]; // stories (fp16)
__device__ __half g_Uth[HH * HH];                   // U^T fp16 [n][k]
__device__ __nv_bfloat16 g_Wthi[HH * HH];
__device__ __nv_bfloat16 g_Wtlo[HH * HH];

// ---------------- helpers ----------------
__device__ __forceinline__ unsigned smem_u32(const void* p) {
    return (unsigned)__cvta_generic_to_shared(p);
}
__device__ __forceinline__ void ldsm_x4(unsigned addr, unsigned& r0, unsigned& r1, unsigned& r2, unsigned& r3) {
    asm volatile("ldmatrix.sync.aligned.m8n8.x4.shared.b16 {%0,%1,%2,%3}, [%4];"
                 : "=r"(r0), "=r"(r1), "=r"(r2), "=r"(r3) : "r"(addr));
}
__device__ __forceinline__ void mma_bf16(float* c, const unsigned* a, unsigned b0, unsigned b1) {
    asm volatile("mma.sync.aligned.m16n8k16.row.col.f32.bf16.bf16.f32 "
                 "{%0,%1,%2,%3}, {%4,%5,%6,%7}, {%8,%9}, {%0,%1,%2,%3};"
                 : "+f"(c[0]), "+f"(c[1]), "+f"(c[2]), "+f"(c[3])
                 : "r"(a[0]), "r"(a[1]), "r"(a[2]), "r"(a[3]), "r"(b0), "r"(b1));
}
__device__ __forceinline__ void mma_f16(float* c, const unsigned* a, unsigned b0, unsigned b1) {
    asm volatile("mma.sync.aligned.m16n8k16.row.col.f32.f16.f16.f32 "
                 "{%0,%1,%2,%3}, {%4,%5,%6,%7}, {%8,%9}, {%0,%1,%2,%3};"
                 : "+f"(c[0]), "+f"(c[1]), "+f"(c[2]), "+f"(c[3])
                 : "r"(a[0]), "r"(a[1]), "r"(a[2]), "r"(a[3]), "r"(b0), "r"(b1));
}
__device__ __forceinline__ void cpasync16(unsigned dst, const void* src) {
    asm volatile("cp.async.cg.shared.global [%0], [%1], 16;" :: "r"(dst), "l"(src));
}
__device__ __forceinline__ unsigned pack2bf(__nv_bfloat16 a, __nv_bfloat16 b) {
    unsigned short ua = *reinterpret_cast<unsigned short*>(&a);
    unsigned short ub = *reinterpret_cast<unsigned short*>(&b);
    return (unsigned)ua | ((unsigned)ub << 16);
}
__device__ __forceinline__ uint32_t h2u(__half2 v) {
    union { __half2 h; uint32_t u; } c; c.h = v; return c.u;
}
__device__ __forceinline__ __half2 u2h(uint32_t v) {
    union { __half2 h; uint32_t u; } c; c.u = v; return c.h;
}
__device__ __forceinline__ void split8(float4 v0, float4 v1, uint4& h, uint4& l) {
    float f[8] = {v0.x, v0.y, v0.z, v0.w, v1.x, v1.y, v1.z, v1.w};
    unsigned hh[4], ll[4];
#pragma unroll
    for (int j = 0; j < 4; j++) {
        float a = f[2 * j], b = f[2 * j + 1];
        __nv_bfloat16 ha = __float2bfloat16(a), hb = __float2bfloat16(b);
        __nv_bfloat16 la = __float2bfloat16(a - __bfloat162float(ha));
        __nv_bfloat16 lb = __float2bfloat16(b - __bfloat162float(hb));
        hh[j] = pack2bf(ha, hb); ll[j] = pack2bf(la, lb);
    }
    h = make_uint4(hh[0], hh[1], hh[2], hh[3]);
    l = make_uint4(ll[0], ll[1], ll[2], ll[3]);
}

// ---------------- prep ----------------
__global__ void split_transpose_kernel(const float* __restrict__ src,
                                       __nv_bfloat16* __restrict__ hi,
                                       __nv_bfloat16* __restrict__ lo) {
    int idx = blockIdx.x * 256 + threadIdx.x;
    int n = idx >> 8, k = idx & 255;
    float x = src[k * 256 + n];
    __nv_bfloat16 h = __float2bfloat16(x);
    hi[idx] = h;
    lo[idx] = __float2bfloat16(x - __bfloat162float(h));
}
__global__ void prep_Uth_kernel(const float* __restrict__ U) {
    int idx = blockIdx.x * 256 + threadIdx.x;
    int n = idx >> 8, k = idx & 255;
    g_Uth[idx] = __float2half(U[k * 256 + n]);
}
__global__ void stories_half_kernel(const float* __restrict__ src) {
    size_t i = ((size_t)blockIdx.x * 256 + threadIdx.x) * 4;
    float4 v = *(const float4*)(src + i);
    __half2* d = (__half2*)(g_storiesh + i);
    d[0] = __float22half2_rn(make_float2(v.x, v.y));
    d[1] = __float22half2_rn(make_float2(v.z, v.w));
}

// ---------------- sentW precompute (bf16 3-pass, fp16 out) ----------------
#define SA_STR 264
#define SA_BYTES (128 * SA_STR * 2)
#define SBC_STR 40
#define SBC_BYTES (256 * SBC_STR * 2)
#define OFF_AHI 0
#define OFF_ALO SA_BYTES
#define OFF_B (2 * SA_BYTES)
#define G_SMEM (OFF_B + 4 * SBC_BYTES + 1024)

__device__ __forceinline__ void g_stage_A(const float* __restrict__ Asrc, char* sm, int tid) {
    __nv_bfloat16* sAhi = (__nv_bfloat16*)(sm + OFF_AHI);
    __nv_bfloat16* sAlo = (__nv_bfloat16*)(sm + OFF_ALO);
    for (int i = tid; i < 128 * 32; i += 512) {
        int row = i >> 5, kq = (i & 31) << 3;
        const float* p = Asrc + row * 256 + kq;
        float4 v0 = *(const float4*)p;
        float4 v1 = *(const float4*)(p + 4);
        uint4 h, l;
        split8(v0, v1, h, l);
        *(uint4*)(sAhi + row * SA_STR + kq) = h;
        *(uint4*)(sAlo + row * SA_STR + kq) = l;
    }
}
__device__ __forceinline__ void g_stage_B(char* sm, const __nv_bfloat16* __restrict__ Bthi,
                                          const __nv_bfloat16* __restrict__ Btlo,
                                          int buf, int kt, int tid) {
    __nv_bfloat16* bh = (__nv_bfloat16*)(sm + OFF_B + buf * 2 * SBC_BYTES);
    __nv_bfloat16* bl = (__nv_bfloat16*)(sm + OFF_B + buf * 2 * SBC_BYTES + SBC_BYTES);
    for (int i = tid; i < 1024; i += 512) {
        int n = i >> 2, g = (i & 3) << 3;
        cpasync16(smem_u32(bh + n * SBC_STR + g), Bthi + n * 256 + kt + g);
        cpasync16(smem_u32(bl + n * SBC_STR + g), Btlo + n * 256 + kt + g);
    }
}

__global__ __launch_bounds__(512, 1) void tc_gemm_kernel(const float* __restrict__ Asrc,
                                                         __half* __restrict__ Cout) {
    extern __shared__ char sm[];
    const int tid = threadIdx.x;
    const int lane = tid & 31, wid = tid >> 5;
    const int wr = wid >> 2, wc = wid & 3;
    const int rb = wr * 32;
    const size_t row0 = (size_t)blockIdx.x * 128;
    const int a_lr = ((lane >> 3) & 1) * 8 + (lane & 7);
    const int a_lc = ((lane >> 4) & 1) * 8;
    const int b_nr = ((lane >> 4) << 3) + (lane & 7);
    const int b_kc = ((lane >> 3) & 1) << 3;
    const unsigned sAhiU = smem_u32(sm + OFF_AHI);
    const unsigned sAloU = smem_u32(sm + OFF_ALO);
    const unsigned sB0 = smem_u32(sm + OFF_B);

    g_stage_A(Asrc + row0 * 256, sm, tid);
    __syncthreads();

    float acc[2][8][4];
#pragma unroll
    for (int i = 0; i < 2; i++)
#pragma unroll
        for (int j = 0; j < 8; j++)
#pragma unroll
            for (int q = 0; q < 4; q++) acc[i][j][q] = 0.f;

    g_stage_B(sm, g_Wthi, g_Wtlo, 0, 0, tid);
    asm volatile("cp.async.commit_group;");

#pragma unroll 2
    for (int c = 0; c < 8; c++) {
        if (c < 7) {
            g_stage_B(sm, g_Wthi, g_Wtlo, (c + 1) & 1, (c + 1) * 32, tid);
            asm volatile("cp.async.commit_group;");
            asm volatile("cp.async.wait_group 1;");
        } else {
            asm volatile("cp.async.wait_group 0;");
        }
        __syncthreads();
        const unsigned sBhiU = sB0 + (c & 1) * 2 * SBC_BYTES;
        const unsigned sBloU = sBhiU + SBC_BYTES;
#pragma unroll
        for (int ks = 0; ks < 2; ks++) {
            int kA = c * 32 + ks * 16;
            unsigned Ah[2][4], Al[2][4];
#pragma unroll
            for (int mi = 0; mi < 2; mi++) {
                unsigned aoff = (unsigned)((rb + mi * 16 + a_lr) * SA_STR + kA + a_lc) * 2;
                ldsm_x4(sAhiU + aoff, Ah[mi][0], Ah[mi][1], Ah[mi][2], Ah[mi][3]);
                ldsm_x4(sAloU + aoff, Al[mi][0], Al[mi][1], Al[mi][2], Al[mi][3]);
            }
#pragma unroll
            for (int np = 0; np < 4; np++) {
                unsigned boff = (unsigned)((wc * 64 + np * 16 + b_nr) * SBC_STR + ks * 16 + b_kc) * 2;
                unsigned Bh[4], Bl[4];
                ldsm_x4(sBhiU + boff, Bh[0], Bh[1], Bh[2], Bh[3]);
                ldsm_x4(sBloU + boff, Bl[0], Bl[1], Bl[2], Bl[3]);
#pragma unroll
                for (int mi = 0; mi < 2; mi++) {
#pragma unroll
                    for (int nj = 0; nj < 2; nj++) {
                        float* cc = acc[mi][np * 2 + nj];
                        mma_bf16(cc, Ah[mi], Bh[2 * nj], Bh[2 * nj + 1]);
                        mma_bf16(cc, Ah[mi], Bl[2 * nj], Bl[2 * nj + 1]);
                        mma_bf16(cc, Al[mi], Bh[2 * nj], Bh[2 * nj + 1]);
                    }
                }
            }
        }
        __syncthreads();
    }

    const int gid = lane >> 2, tig = lane & 3;
#pragma unroll
    for (int mi = 0; mi < 2; mi++) {
        int r0 = rb + mi * 16 + gid, r1 = r0 + 8;
#pragma unroll
        for (int nt = 0; nt < 8; nt++) {
            int C = wc * 64 + nt * 8 + tig * 2;
            float* cc = acc[mi][nt];
            *(__half2*)(Cout + (row0 + r0) * 256 + C) = __float22half2_rn(make_float2(cc[0], cc[1]));
            *(__half2*)(Cout + (row0 + r1) * 256 + C) = __float22half2_rn(make_float2(cc[2], cc[3]));
        }
    }
}

// ========= persistent recurrence (double-buffered state, 2 barriers/step) ==
#define P_SA_STR 264
#define P_SA_BYTES (64 * P_SA_STR * 2)         // 33792 per buffer
#define P_BH_STR 264
#define P_BH_BYTES (256 * P_BH_STR * 2)        // 135168
#define P_OFF_A0 0
#define P_OFF_A1 P_SA_BYTES
#define P_OFF_B (2 * P_SA_BYTES)               // 67584
#define P_OFF_F32 (P_OFF_B + P_BH_BYTES)       // 202752
// f32: keys256 kc256 pa256 gm64 sc64 ss256 g1_256 g2_256
#define P_SMEM (P_OFF_F32 + (256 * 3 + 64 * 2 + 256 * 3) * 4)   // 209168

__global__ __launch_bounds__(256, 1) void persist_kernel(const float* __restrict__ stories,
                                                         const float* __restrict__ mask,
                                                         const float* __restrict__ keys,
                                                         const float* __restrict__ V,
                                                         const float* __restrict__ prelu_a,
                                                         float* __restrict__ out) {
    extern __shared__ char sm[];
    __half* sB = (__half*)(sm + P_OFF_B);
    float* sKeys = (float*)(sm + P_OFF_F32);
    float* sKC = sKeys + 256;
    float* sPA = sKC + 256;
    float* sGm = sPA + 256;   // [64]
    float* sSc = sGm + 64;    // [64]
    float* sSS = sSc + 64;    // [64][4]
    float* sG1 = sSS + 256;   // [64][4]
    float* sG2 = sG1 + 256;   // [64][4]

    const int tid = threadIdx.x;
    const int lane = tid & 31, wid = tid >> 5;
    const int wr = wid >> 2, wc = wid & 3;
    const int rb = wr * 32;
    const int gid = lane >> 2, tig = lane & 3;
    const int m = blockIdx.y;
    const int b0 = blockIdx.x * 64;

    const int a_lr = ((lane >> 3) & 1) * 8 + (lane & 7);
    const int a_lc = ((lane >> 4) & 1) * 8;
    const int b_nr = ((lane >> 4) << 3) + (lane & 7);
    const int b_kc = ((lane >> 3) & 1) << 3;
    const unsigned sBU = smem_u32(sB);
    const unsigned sA0U = smem_u32(sm + P_OFF_A0);

    float* __restrict__ gates_out = out + (size_t)MM * BB * HH;

    sKeys[tid] = keys[m * HH + tid];
    sPA[tid] = prelu_a[tid];
    {   // kc[col] = keys[m,:] . V[:,col]
        float p = 0.f;
        const float* vp = V + tid;
        const float* kp = keys + m * HH;
#pragma unroll 8
        for (int k = 0; k < 256; k++) p += kp[k] * vp[(size_t)k * HH];
        sKC[tid] = p;
    }
    // resident U^T fp16
    for (int i = tid; i < 256 * 32; i += 256) {
        int n = i >> 5, g = (i & 31) << 3;
        *(uint4*)(sB + n * P_BH_STR + g) = *(const uint4*)(g_Uth + n * 256 + g);
    }
    // init state (buffer 0) rows = keys[m] raw, scale 1
    {
        __half* sA0 = (__half*)(sm + P_OFF_A0);
        for (int i = tid; i < 64 * 32; i += 256) {
            int row = i >> 5, kq = (i & 31) << 3;
#pragma unroll
            for (int j = 0; j < 4; j++) {
                float2 kv = *(const float2*)(keys + m * HH + kq + 2 * j);
                *(uint32_t*)(sA0 + row * P_SA_STR + kq + 2 * j) = h2u(__float22half2_rn(kv));
            }
        }
    }
    if (tid < 64) sSc[tid] = 1.0f;
    // gate 0: arg = 2 * dot(keys, sent0_row)
    {
        int gr = tid >> 2, gq = tid & 3;
        const float* srow = stories + ((size_t)(b0 + gr)) * HH + gq * 64;
        const float* kk = sKeys + gq * 64;
        float p = 0.f;
#pragma unroll
        for (int k = 0; k < 64; k += 4) {
            float4 sv = *(const float4*)(srow + k);
            p += kk[k] * sv.x + kk[k + 1] * sv.y + kk[k + 2] * sv.z + kk[k + 3] * sv.w;
        }
        p += __shfl_xor_sync(0xffffffffu, p, 1);
        p += __shfl_xor_sync(0xffffffffu, p, 2);
        if (gq == 0) {
            float g = 1.0f / (1.0f + expf(-2.0f * p));
            gates_out[(size_t)m * BB + b0 + gr] = g;
            sGm[gr] = g * mask[b0 + gr];
        }
    }
    __syncthreads();

    for (int t = 0; t < TT; t++) {
        const unsigned sArU = sA0U + (unsigned)(t & 1) * P_SA_BYTES;          // read buf
        __half* sAr = (__half*)(sm + P_OFF_A0 + (t & 1) * P_SA_BYTES);
        __half* sAw = (__half*)(sm + P_OFF_A0 + ((t + 1) & 1) * P_SA_BYTES);  // write buf

        // ---- mma: D = raw_state @ U (no barrier needed after; per-warp) ----
        float acc[2][8][4];
#pragma unroll
        for (int i = 0; i < 2; i++)
#pragma unroll
            for (int j = 0; j < 8; j++)
#pragma unroll
                for (int q = 0; q < 4; q++) acc[i][j][q] = 0.f;

#pragma unroll 4
        for (int ks = 0; ks < 16; ks++) {
            int kcol = ks * 16;
            unsigned Af[2][4];
#pragma unroll
            for (int mi = 0; mi < 2; mi++) {
                unsigned aoff = (unsigned)((rb + mi * 16 + a_lr) * P_SA_STR + kcol + a_lc) * 2;
                ldsm_x4(sArU + aoff, Af[mi][0], Af[mi][1], Af[mi][2], Af[mi][3]);
            }
#pragma unroll
            for (int np = 0; np < 4; np++) {
                unsigned boff = (unsigned)((wc * 64 + np * 16 + b_nr) * P_BH_STR + kcol + b_kc) * 2;
                unsigned Bf[4];
                ldsm_x4(sBU + boff, Bf[0], Bf[1], Bf[2], Bf[3]);
#pragma unroll
                for (int mi = 0; mi < 2; mi++) {
#pragma unroll
                    for (int nj = 0; nj < 2; nj++)
                        mma_f16(acc[mi][np * 2 + nj], Af[mi], Bf[2 * nj], Bf[2 * nj + 1]);
                }
            }
        }

        // ---- fused epilogue (reads old buf, writes new buf) + gate partials ----
        const int tn = (t < TT - 1) ? t + 1 : t;
        const __half* swb = g_sentWh + ((size_t)t * BB + b0) * HH;
        const __half* seb = g_storiesh + ((size_t)tn * BB + b0) * HH;
#pragma unroll
        for (int mi = 0; mi < 2; mi++) {
            int r0 = rb + mi * 16 + gid, r1 = r0 + 8;
            float gm0 = sGm[r0], gm1 = sGm[r1];
            float s0 = sSc[r0], s1 = sSc[r1];
            float ss0 = 0.f, ss1 = 0.f, g1a = 0.f, g1b = 0.f, g2a = 0.f, g2b = 0.f;
#pragma unroll
            for (int nt = 0; nt < 8; nt++) {
                int C = wc * 64 + nt * 8 + tig * 2;
                float2 kc = *(const float2*)(sKC + C);
                float2 pa = *(const float2*)(sPA + C);
                float2 kv = *(const float2*)(sKeys + C);
                float2 sw0 = __half22float2(*(const __half2*)(swb + (size_t)r0 * 256 + C));
                float2 sw1 = __half22float2(*(const __half2*)(swb + (size_t)r1 * 256 + C));
                float2 se0 = __half22float2(*(const __half2*)(seb + (size_t)r0 * 256 + C));
                float2 se1 = __half22float2(*(const __half2*)(seb + (size_t)r1 * 256 + C));
                float2 o0 = __half22float2(u2h(*(const uint32_t*)(sAr + r0 * P_SA_STR + C)));
                float2 o1 = __half22float2(u2h(*(const uint32_t*)(sAr + r1 * P_SA_STR + C)));
                float* cc = acc[mi][nt];
                float v, n0x, n0y, n1x, n1y;
                v = fmaf(s0, cc[0], kc.x + sw0.x); v = (v >= 0.f) ? v : pa.x * v; n0x = fmaf(gm0, v, s0 * o0.x);
                v = fmaf(s0, cc[1], kc.y + sw0.y); v = (v >= 0.f) ? v : pa.y * v; n0y = fmaf(gm0, v, s0 * o0.y);
                v = fmaf(s1, cc[2], kc.x + sw1.x); v = (v >= 0.f) ? v : pa.x * v; n1x = fmaf(gm1, v, s1 * o1.x);
                v = fmaf(s1, cc[3], kc.y + sw1.y); v = (v >= 0.f) ? v : pa.y * v; n1y = fmaf(gm1, v, s1 * o1.y);
                ss0 = fmaf(n0x, n0x, fmaf(n0y, n0y, ss0));
                ss1 = fmaf(n1x, n1x, fmaf(n1y, n1y, ss1));
                g1a = fmaf(n0x, se0.x, fmaf(n0y, se0.y, g1a));
                g1b = fmaf(n1x, se1.x, fmaf(n1y, se1.y, g1b));
                g2a = fmaf(kv.x, se0.x, fmaf(kv.y, se0.y, g2a));
                g2b = fmaf(kv.x, se1.x, fmaf(kv.y, se1.y, g2b));
                *(uint32_t*)(sAw + r0 * P_SA_STR + C) = h2u(__float22half2_rn(make_float2(n0x, n0y)));
                *(uint32_t*)(sAw + r1 * P_SA_STR + C) = h2u(__float22half2_rn(make_float2(n1x, n1y)));
            }
#pragma unroll
            for (int d = 1; d <= 2; d <<= 1) {
                ss0 += __shfl_xor_sync(0xffffffffu, ss0, d);
                ss1 += __shfl_xor_sync(0xffffffffu, ss1, d);
                g1a += __shfl_xor_sync(0xffffffffu, g1a, d);
                g1b += __shfl_xor_sync(0xffffffffu, g1b, d);
                g2a += __shfl_xor_sync(0xffffffffu, g2a, d);
                g2b += __shfl_xor_sync(0xffffffffu, g2b, d);
            }
            if (tig == 0) {
                sSS[r0 * 4 + wc] = ss0; sSS[r1 * 4 + wc] = ss1;
                sG1[r0 * 4 + wc] = g1a; sG1[r1 * 4 + wc] = g1b;
                sG2[r0 * 4 + wc] = g2a; sG2[r1 * 4 + wc] = g2b;
            }
        }
        __syncthreads();   // bar A: reductions + new state visible

        // ---- finalize: norm scale + next gate ----
        if (tid < 64) {
            int r = tid;
            float ssum = sSS[r * 4] + sSS[r * 4 + 1] + sSS[r * 4 + 2] + sSS[r * 4 + 3];
            float sc = 1.0f / fmaxf(sqrtf(ssum), 1e-12f);
            sSc[r] = sc;
            if (t < TT - 1) {
                float arg = sc * (sG1[r * 4] + sG1[r * 4 + 1] + sG1[r * 4 + 2] + sG1[r * 4 + 3])
                          + (sG2[r * 4] + sG2[r * 4 + 1] + sG2[r * 4 + 2] + sG2[r * 4 + 3]);
                float g = 1.0f / (1.0f + expf(-arg));
                gates_out[((size_t)(t + 1) * MM + m) * BB + b0 + r] = g;
                sGm[r] = g * mask[(t + 1) * BB + b0 + r];
            }
        }
        __syncthreads();   // bar B: sSc/sGm ready for next step's epilogue
    }

    // final output: normalized state (TT even -> state in buffer 0)
    {
        const __half* sAf = (const __half*)(sm + P_OFF_A0);
        for (int i = tid; i < 64 * 256; i += 256) {
            int row = i >> 8, col = i & 255;
            out[((size_t)m * BB + b0 + row) * HH + col] = __half2float(sAf[row * P_SA_STR + col]) * sSc[row];
        }
    }
}

// ---------------------------------------------------------------------------
extern "C" void kernel_launch(void* const* d_in, const int* in_sizes, int n_in,
                              void* d_out, int out_size) {
    const float* stories = (const float*)d_in[0];
    const float* mask    = (const float*)d_in[1];
    const float* keys    = (const float*)d_in[2];
    const float* U       = (const float*)d_in[3];
    const float* W       = (const float*)d_in[4];
    const float* V       = (const float*)d_in[5];
    const float* prelu_a = (const float*)d_in[6];
    float* out = (float*)d_out;

    static bool attr_done = false;
    if (!attr_done) {
        cudaFuncSetAttribute(tc_gemm_kernel, cudaFuncAttributeMaxDynamicSharedMemorySize, G_SMEM);
        cudaFuncSetAttribute(persist_kernel, cudaFuncAttributeMaxDynamicSharedMemorySize, P_SMEM);
        attr_done = true;
    }

    __nv_bfloat16 *wthi, *wtlo;
    cudaGetSymbolAddress((void**)&wthi, g_Wthi);
    cudaGetSymbolAddress((void**)&wtlo, g_Wtlo);
    __half* sentwh;
    cudaGetSymbolAddress((void**)&sentwh, g_sentWh);

    split_transpose_kernel<<<256, 256>>>(W, wthi, wtlo);
    prep_Uth_kernel<<<256, 256>>>(U);
    stories_half_kernel<<<(TT * BB * HH) / 1024, 256>>>(stories);
    tc_gemm_kernel<<<(TT * BB) / 128, 512, G_SMEM>>>(stories, sentwh);

    dim3 grid(BB / 64, MM);
    persist_kernel<<<grid, 256, P_SMEM>>>(stories, mask, keys, V, prelu_a, out);
}

// round 14
// speedup vs baseline: 1.0730x; 1.0039x over previous
#include <cuda_runtime.h>
#include <cuda_fp16.h>
#include <cuda_bf16.h>
#include <math.h>
#include <stdint.h>

#define TT 128
#define BB 512
#define HH 256
#define MM 64

__device__ __half g_sentWh[(size_t)TT * BB * HH];   // stories @ W (fp16)
__device__ __half g_storiesh[(size_t)TT * BB * HH]; // stories (fp16)
__device__ __half g_Uth[HH * HH];                   // U^T fp16 [n][k]
__device__ __nv_bfloat16 g_Wthi[HH * HH];
__device__ __nv_bfloat16 g_Wtlo[HH * HH];

// ---------------- helpers ----------------
__device__ __forceinline__ unsigned smem_u32(const void* p) {
    return (unsigned)__cvta_generic_to_shared(p);
}
__device__ __forceinline__ void ldsm_x4(unsigned addr, unsigned& r0, unsigned& r1, unsigned& r2, unsigned& r3) {
    asm volatile("ldmatrix.sync.aligned.m8n8.x4.shared.b16 {%0,%1,%2,%3}, [%4];"
                 : "=r"(r0), "=r"(r1), "=r"(r2), "=r"(r3) : "r"(addr));
}
__device__ __forceinline__ void mma_bf16(float* c, const unsigned* a, unsigned b0, unsigned b1) {
    asm volatile("mma.sync.aligned.m16n8k16.row.col.f32.bf16.bf16.f32 "
                 "{%0,%1,%2,%3}, {%4,%5,%6,%7}, {%8,%9}, {%0,%1,%2,%3};"
                 : "+f"(c[0]), "+f"(c[1]), "+f"(c[2]), "+f"(c[3])
                 : "r"(a[0]), "r"(a[1]), "r"(a[2]), "r"(a[3]), "r"(b0), "r"(b1));
}
__device__ __forceinline__ void mma_f16(float* c, const unsigned* a, unsigned b0, unsigned b1) {
    asm volatile("mma.sync.aligned.m16n8k16.row.col.f32.f16.f16.f32 "
                 "{%0,%1,%2,%3}, {%4,%5,%6,%7}, {%8,%9}, {%0,%1,%2,%3};"
                 : "+f"(c[0]), "+f"(c[1]), "+f"(c[2]), "+f"(c[3])
                 : "r"(a[0]), "r"(a[1]), "r"(a[2]), "r"(a[3]), "r"(b0), "r"(b1));
}
__device__ __forceinline__ void cpasync16(unsigned dst, const void* src) {
    asm volatile("cp.async.cg.shared.global [%0], [%1], 16;" :: "r"(dst), "l"(src));
}
__device__ __forceinline__ unsigned pack2bf(__nv_bfloat16 a, __nv_bfloat16 b) {
    unsigned short ua = *reinterpret_cast<unsigned short*>(&a);
    unsigned short ub = *reinterpret_cast<unsigned short*>(&b);
    return (unsigned)ua | ((unsigned)ub << 16);
}
__device__ __forceinline__ uint32_t h2u(__half2 v) {
    union { __half2 h; uint32_t u; } c; c.h = v; return c.u;
}
__device__ __forceinline__ __half2 u2h(uint32_t v) {
    union { __half2 h; uint32_t u; } c; c.u = v; return c.h;
}
__device__ __forceinline__ void split8(float4 v0, float4 v1, uint4& h, uint4& l) {
    float f[8] = {v0.x, v0.y, v0.z, v0.w, v1.x, v1.y, v1.z, v1.w};
    unsigned hh[4], ll[4];
#pragma unroll
    for (int j = 0; j < 4; j++) {
        float a = f[2 * j], b = f[2 * j + 1];
        __nv_bfloat16 ha = __float2bfloat16(a), hb = __float2bfloat16(b);
        __nv_bfloat16 la = __float2bfloat16(a - __bfloat162float(ha));
        __nv_bfloat16 lb = __float2bfloat16(b - __bfloat162float(hb));
        hh[j] = pack2bf(ha, hb); ll[j] = pack2bf(la, lb);
    }
    h = make_uint4(hh[0], hh[1], hh[2], hh[3]);
    l = make_uint4(ll[0], ll[1], ll[2], ll[3]);
}

// ---------------- prep ----------------
__global__ void split_transpose_kernel(const float* __restrict__ src,
                                       __nv_bfloat16* __restrict__ hi,
                                       __nv_bfloat16* __restrict__ lo) {
    int idx = blockIdx.x * 256 + threadIdx.x;
    int n = idx >> 8, k = idx & 255;
    float x = src[k * 256 + n];
    __nv_bfloat16 h = __float2bfloat16(x);
    hi[idx] = h;
    lo[idx] = __float2bfloat16(x - __bfloat162float(h));
}
__global__ void prep_Uth_kernel(const float* __restrict__ U) {
    int idx = blockIdx.x * 256 + threadIdx.x;
    int n = idx >> 8, k = idx & 255;
    g_Uth[idx] = __float2half(U[k * 256 + n]);
}
__global__ void stories_half_kernel(const float* __restrict__ src) {
    size_t i = ((size_t)blockIdx.x * 256 + threadIdx.x) * 4;
    float4 v = *(const float4*)(src + i);
    __half2* d = (__half2*)(g_storiesh + i);
    d[0] = __float22half2_rn(make_float2(v.x, v.y));
    d[1] = __float22half2_rn(make_float2(v.z, v.w));
}

// ---------------- sentW precompute (bf16 3-pass, fp16 out) ----------------
#define SA_STR 264
#define SA_BYTES (128 * SA_STR * 2)
#define SBC_STR 40
#define SBC_BYTES (256 * SBC_STR * 2)
#define OFF_AHI 0
#define OFF_ALO SA_BYTES
#define OFF_B (2 * SA_BYTES)
#define G_SMEM (OFF_B + 4 * SBC_BYTES + 1024)

__device__ __forceinline__ void g_stage_A(const float* __restrict__ Asrc, char* sm, int tid) {
    __nv_bfloat16* sAhi = (__nv_bfloat16*)(sm + OFF_AHI);
    __nv_bfloat16* sAlo = (__nv_bfloat16*)(sm + OFF_ALO);
    for (int i = tid; i < 128 * 32; i += 512) {
        int row = i >> 5, kq = (i & 31) << 3;
        const float* p = Asrc + row * 256 + kq;
        float4 v0 = *(const float4*)p;
        float4 v1 = *(const float4*)(p + 4);
        uint4 h, l;
        split8(v0, v1, h, l);
        *(uint4*)(sAhi + row * SA_STR + kq) = h;
        *(uint4*)(sAlo + row * SA_STR + kq) = l;
    }
}
__device__ __forceinline__ void g_stage_B(char* sm, const __nv_bfloat16* __restrict__ Bthi,
                                          const __nv_bfloat16* __restrict__ Btlo,
                                          int buf, int kt, int tid) {
    __nv_bfloat16* bh = (__nv_bfloat16*)(sm + OFF_B + buf * 2 * SBC_BYTES);
    __nv_bfloat16* bl = (__nv_bfloat16*)(sm + OFF_B + buf * 2 * SBC_BYTES + SBC_BYTES);
    for (int i = tid; i < 1024; i += 512) {
        int n = i >> 2, g = (i & 3) << 3;
        cpasync16(smem_u32(bh + n * SBC_STR + g), Bthi + n * 256 + kt + g);
        cpasync16(smem_u32(bl + n * SBC_STR + g), Btlo + n * 256 + kt + g);
    }
}

__global__ __launch_bounds__(512, 1) void tc_gemm_kernel(const float* __restrict__ Asrc,
                                                         __half* __restrict__ Cout) {
    extern __shared__ char sm[];
    const int tid = threadIdx.x;
    const int lane = tid & 31, wid = tid >> 5;
    const int wr = wid >> 2, wc = wid & 3;
    const int rb = wr * 32;
    const size_t row0 = (size_t)blockIdx.x * 128;
    const int a_lr = ((lane >> 3) & 1) * 8 + (lane & 7);
    const int a_lc = ((lane >> 4) & 1) * 8;
    const int b_nr = ((lane >> 4) << 3) + (lane & 7);
    const int b_kc = ((lane >> 3) & 1) << 3;
    const unsigned sAhiU = smem_u32(sm + OFF_AHI);
    const unsigned sAloU = smem_u32(sm + OFF_ALO);
    const unsigned sB0 = smem_u32(sm + OFF_B);

    g_stage_A(Asrc + row0 * 256, sm, tid);
    __syncthreads();

    float acc[2][8][4];
#pragma unroll
    for (int i = 0; i < 2; i++)
#pragma unroll
        for (int j = 0; j < 8; j++)
#pragma unroll
            for (int q = 0; q < 4; q++) acc[i][j][q] = 0.f;

    g_stage_B(sm, g_Wthi, g_Wtlo, 0, 0, tid);
    asm volatile("cp.async.commit_group;");

#pragma unroll 2
    for (int c = 0; c < 8; c++) {
        if (c < 7) {
            g_stage_B(sm, g_Wthi, g_Wtlo, (c + 1) & 1, (c + 1) * 32, tid);
            asm volatile("cp.async.commit_group;");
            asm volatile("cp.async.wait_group 1;");
        } else {
            asm volatile("cp.async.wait_group 0;");
        }
        __syncthreads();
        const unsigned sBhiU = sB0 + (c & 1) * 2 * SBC_BYTES;
        const unsigned sBloU = sBhiU + SBC_BYTES;
#pragma unroll
        for (int ks = 0; ks < 2; ks++) {
            int kA = c * 32 + ks * 16;
            unsigned Ah[2][4], Al[2][4];
#pragma unroll
            for (int mi = 0; mi < 2; mi++) {
                unsigned aoff = (unsigned)((rb + mi * 16 + a_lr) * SA_STR + kA + a_lc) * 2;
                ldsm_x4(sAhiU + aoff, Ah[mi][0], Ah[mi][1], Ah[mi][2], Ah[mi][3]);
                ldsm_x4(sAloU + aoff, Al[mi][0], Al[mi][1], Al[mi][2], Al[mi][3]);
            }
#pragma unroll
            for (int np = 0; np < 4; np++) {
                unsigned boff = (unsigned)((wc * 64 + np * 16 + b_nr) * SBC_STR + ks * 16 + b_kc) * 2;
                unsigned Bh[4], Bl[4];
                ldsm_x4(sBhiU + boff, Bh[0], Bh[1], Bh[2], Bh[3]);
                ldsm_x4(sBloU + boff, Bl[0], Bl[1], Bl[2], Bl[3]);
#pragma unroll
                for (int mi = 0; mi < 2; mi++) {
#pragma unroll
                    for (int nj = 0; nj < 2; nj++) {
                        float* cc = acc[mi][np * 2 + nj];
                        mma_bf16(cc, Ah[mi], Bh[2 * nj], Bh[2 * nj + 1]);
                        mma_bf16(cc, Ah[mi], Bl[2 * nj], Bl[2 * nj + 1]);
                        mma_bf16(cc, Al[mi], Bh[2 * nj], Bh[2 * nj + 1]);
                    }
                }
            }
        }
        __syncthreads();
    }

    const int gid = lane >> 2, tig = lane & 3;
#pragma unroll
    for (int mi = 0; mi < 2; mi++) {
        int r0 = rb + mi * 16 + gid, r1 = r0 + 8;
#pragma unroll
        for (int nt = 0; nt < 8; nt++) {
            int C = wc * 64 + nt * 8 + tig * 2;
            float* cc = acc[mi][nt];
            *(__half2*)(Cout + (row0 + r0) * 256 + C) = __float22half2_rn(make_float2(cc[0], cc[1]));
            *(__half2*)(Cout + (row0 + r1) * 256 + C) = __float22half2_rn(make_float2(cc[2], cc[3]));
        }
    }
}

// ==== persistent recurrence: double-buffered state, 1 barrier/step =========
#define P_SA_STR 264
#define P_SA_BYTES (64 * P_SA_STR * 2)         // 33792 per buffer
#define P_BH_STR 264
#define P_BH_BYTES (256 * P_BH_STR * 2)        // 135168
#define P_OFF_A0 0
#define P_OFF_B (2 * P_SA_BYTES)               // 67584
#define P_OFF_F32 (P_OFF_B + P_BH_BYTES)       // 202752
// f32: keys256 kc256 pa256 red[2][768] tmp64
#define P_SMEM (P_OFF_F32 + (256 * 3 + 2 * 768 + 64) * 4)   // 212224

__global__ __launch_bounds__(256, 1) void persist_kernel(const float* __restrict__ stories,
                                                         const float* __restrict__ mask,
                                                         const float* __restrict__ keys,
                                                         const float* __restrict__ V,
                                                         const float* __restrict__ prelu_a,
                                                         float* __restrict__ out) {
    extern __shared__ char sm[];
    __half* sB = (__half*)(sm + P_OFF_B);
    float* sKeys = (float*)(sm + P_OFF_F32);
    float* sKC  = sKeys + 256;
    float* sPA  = sKC + 256;
    float* sRed = sPA + 256;      // [2][768]: ss[256] g1[256] g2[256] per parity
    float* sTmp = sRed + 1536;    // [64]

    const int tid = threadIdx.x;
    const int lane = tid & 31, wid = tid >> 5;
    const int wr = wid >> 2, wc = wid & 3;
    const int rb = wr * 32;
    const int gid = lane >> 2, tig = lane & 3;
    const int m = blockIdx.y;
    const int b0 = blockIdx.x * 64;

    const int a_lr = ((lane >> 3) & 1) * 8 + (lane & 7);
    const int a_lc = ((lane >> 4) & 1) * 8;
    const int b_nr = ((lane >> 4) << 3) + (lane & 7);
    const int b_kc = ((lane >> 3) & 1) << 3;
    const unsigned sBU = smem_u32(sB);
    const unsigned sA0U = smem_u32(sm + P_OFF_A0);

    float* __restrict__ gates_out = out + (size_t)MM * BB * HH;

    sKeys[tid] = keys[m * HH + tid];
    sPA[tid] = prelu_a[tid];
    {   // kc[col] = keys[m,:] . V[:,col]
        float p = 0.f;
        const float* vp = V + tid;
        const float* kp = keys + m * HH;
#pragma unroll 8
        for (int k = 0; k < 256; k++) p += kp[k] * vp[(size_t)k * HH];
        sKC[tid] = p;
    }
    // resident U^T fp16
    for (int i = tid; i < 256 * 32; i += 256) {
        int n = i >> 5, g = (i & 31) << 3;
        *(uint4*)(sB + n * P_BH_STR + g) = *(const uint4*)(g_Uth + n * 256 + g);
    }
    // init state (buffer 0) rows = keys[m] raw, scale 1
    {
        __half* sA0 = (__half*)(sm + P_OFF_A0);
        for (int i = tid; i < 64 * 32; i += 256) {
            int row = i >> 5, kq = (i & 31) << 3;
#pragma unroll
            for (int j = 0; j < 4; j++) {
                float2 kv = *(const float2*)(keys + m * HH + kq + 2 * j);
                *(uint32_t*)(sA0 + row * P_SA_STR + kq + 2 * j) = h2u(__float22half2_rn(kv));
            }
        }
    }
    // gate 0: arg = 2 * dot(keys, sent0_row) -> sTmp holds gm
    {
        int gr = tid >> 2, gq = tid & 3;
        const float* srow = stories + ((size_t)(b0 + gr)) * HH + gq * 64;
        const float* kk = sKeys + gq * 64;
        float p = 0.f;
#pragma unroll
        for (int k = 0; k < 64; k += 4) {
            float4 sv = *(const float4*)(srow + k);
            p += kk[k] * sv.x + kk[k + 1] * sv.y + kk[k + 2] * sv.z + kk[k + 3] * sv.w;
        }
        p += __shfl_xor_sync(0xffffffffu, p, 1);
        p += __shfl_xor_sync(0xffffffffu, p, 2);
        if (gq == 0) {
            float g = 1.0f / (1.0f + expf(-2.0f * p));
            gates_out[(size_t)m * BB + b0 + gr] = g;
            sTmp[gr] = g * mask[b0 + gr];
        }
    }
    __syncthreads();

    // per-thread carried scale/gate for rows rb + j*8 + gid (j = mi*2 + half)
    float sc_r[4], gm_r[4];
#pragma unroll
    for (int j = 0; j < 4; j++) {
        sc_r[j] = 1.0f;
        gm_r[j] = sTmp[rb + j * 8 + gid];
    }

    for (int t = 0; t < TT; t++) {
        const unsigned sArU = sA0U + (unsigned)(t & 1) * P_SA_BYTES;          // read buf
        __half* sAr = (__half*)(sm + P_OFF_A0 + (t & 1) * P_SA_BYTES);
        __half* sAw = (__half*)(sm + P_OFF_A0 + ((t + 1) & 1) * P_SA_BYTES);  // write buf

        // ---- mma: D = raw_state @ U ----
        float acc[2][8][4];
#pragma unroll
        for (int i = 0; i < 2; i++)
#pragma unroll
            for (int j = 0; j < 8; j++)
#pragma unroll
                for (int q = 0; q < 4; q++) acc[i][j][q] = 0.f;

#pragma unroll 4
        for (int ks = 0; ks < 16; ks++) {
            int kcol = ks * 16;
            unsigned Af[2][4];
#pragma unroll
            for (int mi = 0; mi < 2; mi++) {
                unsigned aoff = (unsigned)((rb + mi * 16 + a_lr) * P_SA_STR + kcol + a_lc) * 2;
                ldsm_x4(sArU + aoff, Af[mi][0], Af[mi][1], Af[mi][2], Af[mi][3]);
            }
#pragma unroll
            for (int np = 0; np < 4; np++) {
                unsigned boff = (unsigned)((wc * 64 + np * 16 + b_nr) * P_BH_STR + kcol + b_kc) * 2;
                unsigned Bf[4];
                ldsm_x4(sBU + boff, Bf[0], Bf[1], Bf[2], Bf[3]);
#pragma unroll
                for (int mi = 0; mi < 2; mi++) {
#pragma unroll
                    for (int nj = 0; nj < 2; nj++)
                        mma_f16(acc[mi][np * 2 + nj], Af[mi], Bf[2 * nj], Bf[2 * nj + 1]);
                }
            }
        }

        // ---- fused epilogue + gate partials (writes new buf, parity sRed) ----
        const int tn = (t < TT - 1) ? t + 1 : t;
        const __half* swb = g_sentWh + ((size_t)t * BB + b0) * HH;
        const __half* seb = g_storiesh + ((size_t)tn * BB + b0) * HH;
        float* R = sRed + (t & 1) * 768;
#pragma unroll
        for (int mi = 0; mi < 2; mi++) {
            int r0 = rb + mi * 16 + gid, r1 = r0 + 8;
            float gm0 = gm_r[mi * 2], gm1 = gm_r[mi * 2 + 1];
            float s0 = sc_r[mi * 2], s1 = sc_r[mi * 2 + 1];
            float ss0 = 0.f, ss1 = 0.f, g1a = 0.f, g1b = 0.f, g2a = 0.f, g2b = 0.f;
#pragma unroll
            for (int nt = 0; nt < 8; nt++) {
                int C = wc * 64 + nt * 8 + tig * 2;
                float2 kc = *(const float2*)(sKC + C);
                float2 pa = *(const float2*)(sPA + C);
                float2 kv = *(const float2*)(sKeys + C);
                float2 sw0 = __half22float2(*(const __half2*)(swb + (size_t)r0 * 256 + C));
                float2 sw1 = __half22float2(*(const __half2*)(swb + (size_t)r1 * 256 + C));
                float2 se0 = __half22float2(*(const __half2*)(seb + (size_t)r0 * 256 + C));
                float2 se1 = __half22float2(*(const __half2*)(seb + (size_t)r1 * 256 + C));
                float2 o0 = __half22float2(u2h(*(const uint32_t*)(sAr + r0 * P_SA_STR + C)));
                float2 o1 = __half22float2(u2h(*(const uint32_t*)(sAr + r1 * P_SA_STR + C)));
                float* cc = acc[mi][nt];
                float v, n0x, n0y, n1x, n1y;
                v = fmaf(s0, cc[0], kc.x + sw0.x); v = (v >= 0.f) ? v : pa.x * v; n0x = fmaf(gm0, v, s0 * o0.x);
                v = fmaf(s0, cc[1], kc.y + sw0.y); v = (v >= 0.f) ? v : pa.y * v; n0y = fmaf(gm0, v, s0 * o0.y);
                v = fmaf(s1, cc[2], kc.x + sw1.x); v = (v >= 0.f) ? v : pa.x * v; n1x = fmaf(gm1, v, s1 * o1.x);
                v = fmaf(s1, cc[3], kc.y + sw1.y); v = (v >= 0.f) ? v : pa.y * v; n1y = fmaf(gm1, v, s1 * o1.y);
                ss0 = fmaf(n0x, n0x, fmaf(n0y, n0y, ss0));
                ss1 = fmaf(n1x, n1x, fmaf(n1y, n1y, ss1));
                g1a = fmaf(n0x, se0.x, fmaf(n0y, se0.y, g1a));
                g1b = fmaf(n1x, se1.x, fmaf(n1y, se1.y, g1b));
                g2a = fmaf(kv.x, se0.x, fmaf(kv.y, se0.y, g2a));
                g2b = fmaf(kv.x, se1.x, fmaf(kv.y, se1.y, g2b));
                *(uint32_t*)(sAw + r0 * P_SA_STR + C) = h2u(__float22half2_rn(make_float2(n0x, n0y)));
                *(uint32_t*)(sAw + r1 * P_SA_STR + C) = h2u(__float22half2_rn(make_float2(n1x, n1y)));
            }
#pragma unroll
            for (int d = 1; d <= 2; d <<= 1) {
                ss0 += __shfl_xor_sync(0xffffffffu, ss0, d);
                ss1 += __shfl_xor_sync(0xffffffffu, ss1, d);
                g1a += __shfl_xor_sync(0xffffffffu, g1a, d);
                g1b += __shfl_xor_sync(0xffffffffu, g1b, d);
                g2a += __shfl_xor_sync(0xffffffffu, g2a, d);
                g2b += __shfl_xor_sync(0xffffffffu, g2b, d);
            }
            if (tig == 0) {
                R[r0 * 4 + wc] = ss0;       R[r1 * 4 + wc] = ss1;
                R[256 + r0 * 4 + wc] = g1a; R[256 + r1 * 4 + wc] = g1b;
                R[512 + r0 * 4 + wc] = g2a; R[512 + r1 * 4 + wc] = g2b;
            }
        }
        __syncthreads();   // single barrier: new state + partials visible

        // ---- finalize (redundant per col-group warp, fully parallel) ----
        {
            int rj = rb + tig * 8 + gid;
            float ssum = R[rj * 4] + R[rj * 4 + 1] + R[rj * 4 + 2] + R[rj * 4 + 3];
            float sc = 1.0f / fmaxf(sqrtf(ssum), 1e-12f);
            float gmv = 0.f;
            if (t < TT - 1) {
                float g1s = R[256 + rj * 4] + R[256 + rj * 4 + 1] + R[256 + rj * 4 + 2] + R[256 + rj * 4 + 3];
                float g2s = R[512 + rj * 4] + R[512 + rj * 4 + 1] + R[512 + rj * 4 + 2] + R[512 + rj * 4 + 3];
                float g = 1.0f / (1.0f + expf(-(fmaf(sc, g1s, g2s))));
                if (wc == 0) gates_out[((size_t)(t + 1) * MM + m) * BB + b0 + rj] = g;
                gmv = g * mask[(t + 1) * BB + b0 + rj];
            } else if (wc == 0) {
                sTmp[rj] = sc;
            }
#pragma unroll
            for (int j = 0; j < 4; j++) {
                sc_r[j] = __shfl_sync(0xffffffffu, sc, gid * 4 + j);
                gm_r[j] = __shfl_sync(0xffffffffu, gmv, gid * 4 + j);
            }
        }
    }
    __syncthreads();   // sTmp (final scales) visible

    // final output: normalized state (TT even -> state in buffer 0)
    {
        const __half* sAf = (const __half*)(sm + P_OFF_A0);
        for (int i = tid; i < 64 * 256; i += 256) {
            int row = i >> 8, col = i & 255;
            out[((size_t)m * BB + b0 + row) * HH + col] = __half2float(sAf[row * P_SA_STR + col]) * sTmp[row];
        }
    }
}

// ---------------------------------------------------------------------------
extern "C" void kernel_launch(void* const* d_in, const int* in_sizes, int n_in,
                              void* d_out, int out_size) {
    const float* stories = (const float*)d_in[0];
    const float* mask    = (const float*)d_in[1];
    const float* keys    = (const float*)d_in[2];
    const float* U       = (const float*)d_in[3];
    const float* W       = (const float*)d_in[4];
    const float* V       = (const float*)d_in[5];
    const float* prelu_a = (const float*)d_in[6];
    float* out = (float*)d_out;

    static bool attr_done = false;
    if (!attr_done) {
        cudaFuncSetAttribute(tc_gemm_kernel, cudaFuncAttributeMaxDynamicSharedMemorySize, G_SMEM);
        cudaFuncSetAttribute(persist_kernel, cudaFuncAttributeMaxDynamicSharedMemorySize, P_SMEM);
        attr_done = true;
    }

    __nv_bfloat16 *wthi, *wtlo;
    cudaGetSymbolAddress((void**)&wthi, g_Wthi);
    cudaGetSymbolAddress((void**)&wtlo, g_Wtlo);
    __half* sentwh;
    cudaGetSymbolAddress((void**)&sentwh, g_sentWh);

    split_transpose_kernel<<<256, 256>>>(W, wthi, wtlo);
    prep_Uth_kernel<<<256, 256>>>(U);
    stories_half_kernel<<<(TT * BB * HH) / 1024, 256>>>(stories);
    tc_gemm_kernel<<<(TT * BB) / 128, 512, G_SMEM>>>(stories, sentwh);

    dim3 grid(BB / 64, MM);
    persist_kernel<<<grid, 256, P_SMEM>>>(stories, mask, keys, V, prelu_a, out);
}